// round 15
// baseline (speedup 1.0000x reference)
#include <cuda_runtime.h>
#include <cuda_fp16.h>
#include <cstdint>

#define BATCH 4
#define SEQ   4096
#define DIN   128
#define DOUT  64
#define BQ    128
#define BK    64
#define NTILES 32          // per key-half: 2048/64

// Q pre-scale: 1/sqrt(64) * log2(e)  (softmax runs in exp2 domain)
#define QSCALE 0.1803368801111244f

// ---- fp16 scratch — device globals, no allocation ----
__device__ __half g_qh[BATCH * SEQ * DOUT];
__device__ __half g_ql[BATCH * SEQ * DOUT];
__device__ __half g_kh[BATCH * SEQ * DOUT];
__device__ __half g_kl[BATCH * SEQ * DOUT];
__device__ __half g_vt[BATCH * DOUT * SEQ];   // transposed: [b][dout][seq]

// ---- attn smem ----
#define QH_B       0
#define QL_B       18432
#define KV_B(h, s) (36864 + (h) * 82944 + (s) * 27648)
#define KH_O       0
#define KL_O       9216
#define VT_O       18432
#define SMEM_BYTES 202752

typedef unsigned long long u64;

__device__ __forceinline__ uint32_t smem_u32(const void* p) {
    uint32_t a;
    asm("{ .reg .u64 t; cvta.to.shared.u64 t, %1; cvt.u32.u64 %0, t; }" : "=r"(a) : "l"(p));
    return a;
}
__device__ __forceinline__ void cp16(uint32_t dst, const void* src) {
    asm volatile("cp.async.cg.shared.global [%0], [%1], 16;" :: "r"(dst), "l"(src));
}
#define CP_COMMIT() asm volatile("cp.async.commit_group;" ::: "memory")
#define CP_WAIT1()  asm volatile("cp.async.wait_group 1;" ::: "memory")
#define CP_WAIT2()  asm volatile("cp.async.wait_group 2;" ::: "memory")
#define BARG(id)    asm volatile("bar.sync %0, 256;" :: "r"(id) : "memory")

__device__ __forceinline__ float ex2f(float x) {
    float r; asm("ex2.approx.ftz.f32 %0, %1;" : "=f"(r) : "f"(x)); return r;
}

#define MMA16816(c, a0, a1, a2, a3, b0, b1) \
    asm volatile("mma.sync.aligned.m16n8k16.row.col.f32.f16.f16.f32 " \
                 "{%0,%1,%2,%3}, {%4,%5,%6,%7}, {%8,%9}, {%0,%1,%2,%3};" \
                 : "+f"((c)[0]), "+f"((c)[1]), "+f"((c)[2]), "+f"((c)[3]) \
                 : "r"(a0), "r"(a1), "r"(a2), "r"(a3), "r"(b0), "r"(b1))

#define LDMX4(r0, r1, r2, r3, a) \
    asm volatile("ldmatrix.sync.aligned.m8n8.x4.shared.b16 {%0,%1,%2,%3}, [%4];" \
                 : "=r"(r0), "=r"(r1), "=r"(r2), "=r"(r3) : "r"(a))

// ---------------------------------------------------------------------------
// Kernel 1: QKV projection via tensor cores (unchanged R13).
// ---------------------------------------------------------------------------
#define QP_STRIDE 272
#define XH2_B   0
#define XL2_B   34816
#define WH2_B   69632
#define WL2_B   121856
#define VTS2_B  174080
#define VTS_PAD 136
#define QKV_SMEM 191488

__global__ __launch_bounds__(512)
void qkv_proj_kernel(const float* __restrict__ x,
                     const float* __restrict__ w) {
    extern __shared__ __align__(128) char qsm[];
    const uint32_t smb = smem_u32(qsm);
    __half* xh  = (__half*)(qsm + XH2_B);
    __half* xl  = (__half*)(qsm + XL2_B);
    __half* wh  = (__half*)(qsm + WH2_B);
    __half* wl  = (__half*)(qsm + WL2_B);
    __half* vts = (__half*)(qsm + VTS2_B);

    const int b   = blockIdx.y;
    const int n0  = blockIdx.x * 128;
    const int tid = threadIdx.x;

#pragma unroll
    for (int i = 0; i < 48; i++) {
        const int idx = tid + i * 512;
        const int p = idx >> 13;
        const int rem = idx & 8191;
        const int d = rem >> 6, e = rem & 63;
        float v = w[idx];
        if (p == 0) v *= QSCALE;
        const __half h = __float2half_rn(v);
        const int row = p * 64 + e;
        wh[row * 136 + d] = h;
        wl[row * 136 + d] = __float2half_rn(v - __half2float(h));
    }
    const float* xg = x + ((size_t)(b * SEQ + n0)) * DIN;
#pragma unroll
    for (int i = 0; i < 32; i++) {
        const int idx = tid + i * 512;
        const int tok = idx >> 7, d = idx & 127;
        const float v = xg[idx];
        const __half h = __float2half_rn(v);
        xh[tok * 136 + d] = h;
        xl[tok * 136 + d] = __float2half_rn(v - __half2float(h));
    }
    __syncthreads();

    const int wid  = tid >> 5;
    const int lane = tid & 31;
    const int g    = lane >> 2;
    const int tq   = lane & 3;
    const int pairw = wid >> 1;
    const int halfn = wid & 1;
    const int r0    = pairw * 16;

    const int lt = lane >> 3, lr = lane & 7;
    const uint32_t aoff = (uint32_t)((r0 + ((lt & 1) << 3) + lr) * QP_STRIDE + ((lt >> 1) << 4));
    const uint32_t boff = (uint32_t)((((lane >> 4) << 3) + lr) * QP_STRIDE + ((lt & 1) << 4));

    float acc[12][4];
#pragma unroll
    for (int j = 0; j < 12; j++)
#pragma unroll
        for (int k = 0; k < 4; k++) acc[j][k] = 0.f;

#pragma unroll
    for (int ks = 0; ks < 8; ks++) {
        uint32_t ah0, ah1, ah2, ah3, al0, al1, al2, al3;
        LDMX4(ah0, ah1, ah2, ah3, smb + XH2_B + aoff + ks * 32);
        LDMX4(al0, al1, al2, al3, smb + XL2_B + aoff + ks * 32);
#pragma unroll
        for (int jp = 0; jp < 6; jp++) {
            const uint32_t bb = (uint32_t)((halfn * 96 + jp * 16) * QP_STRIDE) + boff + ks * 32;
            uint32_t bh0, bh1, bh2, bh3, bl0, bl1, bl2, bl3;
            LDMX4(bh0, bh1, bh2, bh3, smb + WH2_B + bb);
            LDMX4(bl0, bl1, bl2, bl3, smb + WL2_B + bb);
            MMA16816(acc[2*jp],   ah0, ah1, ah2, ah3, bh0, bh1);
            MMA16816(acc[2*jp+1], ah0, ah1, ah2, ah3, bh2, bh3);
            MMA16816(acc[2*jp],   ah0, ah1, ah2, ah3, bl0, bl1);
            MMA16816(acc[2*jp+1], ah0, ah1, ah2, ah3, bl2, bl3);
            MMA16816(acc[2*jp],   al0, al1, al2, al3, bh0, bh1);
            MMA16816(acc[2*jp+1], al0, al1, al2, al3, bh2, bh3);
        }
    }

#pragma unroll
    for (int j = 0; j < 12; j++) {
        const int col = halfn * 96 + j * 8 + 2 * tq;
        const int p = col >> 6, e = col & 63;
        const int rowA = r0 + g, rowB = r0 + g + 8;
#pragma unroll
        for (int h2 = 0; h2 < 2; h2++) {
            const int row = h2 ? rowB : rowA;
            const float v0 = acc[j][h2 * 2], v1 = acc[j][h2 * 2 + 1];
            if (p == 2) {
                vts[e * VTS_PAD + row]       = __float2half_rn(v0);
                vts[(e + 1) * VTS_PAD + row] = __float2half_rn(v1);
            } else {
                const __half h0 = __float2half_rn(v0), h1 = __float2half_rn(v1);
                const __half l0 = __float2half_rn(v0 - __half2float(h0));
                const __half l1 = __float2half_rn(v1 - __half2float(h1));
                const size_t go = (size_t)(b * SEQ + n0 + row) * DOUT + e;
                if (p == 0) {
                    *(__half2*)&g_qh[go] = __halves2half2(h0, h1);
                    *(__half2*)&g_ql[go] = __halves2half2(l0, l1);
                } else {
                    *(__half2*)&g_kh[go] = __halves2half2(h0, h1);
                    *(__half2*)&g_kl[go] = __halves2half2(l0, l1);
                }
            }
        }
    }
    __syncthreads();

    const int e = tid >> 3, seg = tid & 7;
    const __half* srcv = vts + e * VTS_PAD + seg * 16;
    uint4* dstv = (uint4*)&g_vt[(((size_t)(b * DOUT + e)) << 12) + n0 + seg * 16];
    dstv[0] = *(const uint4*)(srcv);
    dstv[1] = *(const uint4*)(srcv + 8);
}

// ---------------------------------------------------------------------------
// Kernel 2: flash attention. Warp->half remapped so each SMSP hosts both
// barrier groups (half = (wid>>2)&1) -> anti-phase overlap per scheduler.
// ---------------------------------------------------------------------------
__device__ __forceinline__ void load_kv_h(uint32_t kb, int b, int kt, int htid) {
    const __half* kh = g_kh + ((size_t)(b * SEQ + kt)) * DOUT;
    const __half* kl = g_kl + ((size_t)(b * SEQ + kt)) * DOUT;
    const __half* vt = g_vt + (((size_t)b * DOUT) << 12) + kt;
#pragma unroll
    for (int i = 0; i < 2; i++) {
        const int id = htid + i * 256;
        const int row = id >> 3, c = id & 7;
        cp16(kb + KH_O + row * 144 + c * 16, kh + row * DOUT + c * 8);
        cp16(kb + KL_O + row * 144 + c * 16, kl + row * DOUT + c * 8);
        cp16(kb + VT_O + row * 144 + c * 16, vt + ((size_t)row << 12) + c * 8);
    }
}

__global__ __launch_bounds__(512, 1)
void attn_kernel(float* __restrict__ out) {
    extern __shared__ __align__(128) char sm[];
    const uint32_t smb = smem_u32(sm);
    const int tid  = threadIdx.x;
    const int wid  = tid >> 5;
    const int lane = tid & 31;
    const int g    = lane >> 2;
    const int tq   = lane & 3;
    // remap: SMSP (wid%4) hosts 2 warps of each half
    const int half = (wid >> 2) & 1;
    const int pair = (wid & 3) | ((wid >> 3) << 2);
    const int htid = pair * 32 + lane;
    const int b    = blockIdx.y;
    const int q0   = blockIdx.x * BQ;
    const int r0   = pair * 16;
    const int k0   = half * 2048;

    const int lt = lane >> 3, lr = lane & 7;
    const uint32_t aoff = (uint32_t)((r0 + ((lt & 1) << 3) + lr) * 144 + ((lt >> 1) << 4));
    const uint32_t boff = (uint32_t)((((lane >> 4) << 3) + lr) * 144 + ((lt & 1) << 4));

    const uint32_t bON = (g == 0) ? 0x3C003C00u : 0u;

    {
        const __half* qh = g_qh + ((size_t)(b * SEQ + q0)) * DOUT;
        const __half* ql = g_ql + ((size_t)(b * SEQ + q0)) * DOUT;
#pragma unroll
        for (int i = 0; i < 2; i++) {
            const int id = tid + i * 512;
            const int row = id >> 3, c = id & 7;
            cp16(smb + QH_B + row * 144 + c * 16, qh + row * DOUT + c * 8);
            cp16(smb + QL_B + row * 144 + c * 16, ql + row * DOUT + c * 8);
        }
        CP_COMMIT();
        load_kv_h(smb + KV_B(half, 0), b, k0, htid);
        CP_COMMIT();
        load_kv_h(smb + KV_B(half, 1), b, k0 + BK, htid);
        CP_COMMIT();
    }
    CP_WAIT2();
    __syncthreads();

    float o[8][4], oL[4];
#pragma unroll
    for (int j = 0; j < 8; j++)
#pragma unroll
        for (int k = 0; k < 4; k++) o[j][k] = 0.f;
#pragma unroll
    for (int k = 0; k < 4; k++) oL[k] = 0.f;
    float m0 = -3.0e38f, m1 = -3.0e38f;

    for (int t = 0; t < NTILES; t++) {
        CP_WAIT1();
        BARG(1 + half);
        if (t + 2 < NTILES)
            load_kv_h(smb + KV_B(half, (t + 2) % 3), b, k0 + (t + 2) * BK, htid);
        CP_COMMIT();

        const uint32_t kvb = smb + KV_B(half, t % 3);
        const uint32_t khb = kvb + KH_O + boff;
        const uint32_t klb = kvb + KL_O + boff;
        const uint32_t vtb = kvb + VT_O + boff;

        float s[8][4];
#pragma unroll
        for (int j = 0; j < 8; j++)
#pragma unroll
            for (int k = 0; k < 4; k++) s[j][k] = 0.f;

#pragma unroll
        for (int ks = 0; ks < 4; ks++) {
            uint32_t ah0, ah1, ah2, ah3, al0, al1, al2, al3;
            LDMX4(ah0, ah1, ah2, ah3, smb + QH_B + aoff + ks * 32);
            LDMX4(al0, al1, al2, al3, smb + QL_B + aoff + ks * 32);
#pragma unroll
            for (int jp = 0; jp < 4; jp++) {
                uint32_t bh0, bh1, bh2, bh3, bl0, bl1, bl2, bl3;
                LDMX4(bh0, bh1, bh2, bh3, khb + jp * 2304 + ks * 32);
                LDMX4(bl0, bl1, bl2, bl3, klb + jp * 2304 + ks * 32);
                MMA16816(s[2*jp],   ah0, ah1, ah2, ah3, bh0, bh1);
                MMA16816(s[2*jp+1], ah0, ah1, ah2, ah3, bh2, bh3);
                MMA16816(s[2*jp],   ah0, ah1, ah2, ah3, bl0, bl1);
                MMA16816(s[2*jp+1], ah0, ah1, ah2, ah3, bl2, bl3);
                MMA16816(s[2*jp],   al0, al1, al2, al3, bh0, bh1);
                MMA16816(s[2*jp+1], al0, al1, al2, al3, bh2, bh3);
            }
        }

        float mx0 = -3.0e38f, mx1 = -3.0e38f;
#pragma unroll
        for (int j = 0; j < 8; j++) {
            mx0 = fmaxf(mx0, fmaxf(s[j][0], s[j][1]));
            mx1 = fmaxf(mx1, fmaxf(s[j][2], s[j][3]));
        }
        mx0 = fmaxf(mx0, __shfl_xor_sync(0xffffffffu, mx0, 1));
        mx0 = fmaxf(mx0, __shfl_xor_sync(0xffffffffu, mx0, 2));
        mx1 = fmaxf(mx1, __shfl_xor_sync(0xffffffffu, mx1, 1));
        mx1 = fmaxf(mx1, __shfl_xor_sync(0xffffffffu, mx1, 2));

        const bool active = __any_sync(0xffffffffu,
                                       (mx0 > m0 - 25.f) | (mx1 > m1 - 25.f));
        if (!active) continue;

        const float mn0 = fmaxf(m0, mx0), mn1 = fmaxf(m1, mx1);
        const bool upd = __any_sync(0xffffffffu, (mx0 > m0) | (mx1 > m1));
        if (upd) {
            const float c0 = ex2f(m0 - mn0), c1 = ex2f(m1 - mn1);
#pragma unroll
            for (int j = 0; j < 8; j++) {
                o[j][0] *= c0; o[j][1] *= c0;
                o[j][2] *= c1; o[j][3] *= c1;
            }
            oL[0] *= c0; oL[1] *= c0;
            oL[2] *= c1; oL[3] *= c1;
            m0 = mn0; m1 = mn1;
        }

        uint32_t pa[4][4];
#pragma unroll
        for (int j = 0; j < 8; j++) {
            const float e0 = ex2f(s[j][0] - m0), e1 = ex2f(s[j][1] - m0);
            const float e2 = ex2f(s[j][2] - m1), e3 = ex2f(s[j][3] - m1);
            const __half2 h01 = __floats2half2_rn(e0, e1);
            const __half2 h23 = __floats2half2_rn(e2, e3);
            pa[j >> 1][(j & 1) * 2 + 0] = *(const uint32_t*)&h01;
            pa[j >> 1][(j & 1) * 2 + 1] = *(const uint32_t*)&h23;
        }

#pragma unroll
        for (int ks = 0; ks < 4; ks++) {
#pragma unroll
            for (int jp = 0; jp < 4; jp++) {
                uint32_t v0, v1, v2, v3;
                LDMX4(v0, v1, v2, v3, vtb + jp * 2304 + ks * 32);
                MMA16816(o[2*jp],   pa[ks][0], pa[ks][1], pa[ks][2], pa[ks][3], v0, v1);
                MMA16816(o[2*jp+1], pa[ks][0], pa[ks][1], pa[ks][2], pa[ks][3], v2, v3);
            }
            MMA16816(oL, pa[ks][0], pa[ks][1], pa[ks][2], pa[ks][3], bON, bON);
        }
    }

    const int qlead = lane & ~3;
    const float l0 = __shfl_sync(0xffffffffu, oL[0], qlead);
    const float l1 = __shfl_sync(0xffffffffu, oL[2], qlead);

    __syncthreads();
    float* xo = (float*)sm;
    float* xm = (float*)(sm + 8 * 16 * 68 * 4);

    if (half == 1) {
#pragma unroll
        for (int j = 0; j < 8; j++) {
            const int col = j * 8 + 2 * tq;
            *(float2*)&xo[(r0 + g) * 68 + col]     = make_float2(o[j][0], o[j][1]);
            *(float2*)&xo[(r0 + g + 8) * 68 + col] = make_float2(o[j][2], o[j][3]);
        }
        if (tq == 0) {
            xm[(r0 + g) * 2]         = m0;  xm[(r0 + g) * 2 + 1]     = l0;
            xm[(r0 + g + 8) * 2]     = m1;  xm[(r0 + g + 8) * 2 + 1] = l1;
        }
    }
    __syncthreads();

    if (half == 0) {
        const float mo0 = xm[(r0 + g) * 2],     lo0 = xm[(r0 + g) * 2 + 1];
        const float mo1 = xm[(r0 + g + 8) * 2], lo1 = xm[(r0 + g + 8) * 2 + 1];
        const float mm0 = fmaxf(m0, mo0), mm1 = fmaxf(m1, mo1);
        const float ce0 = ex2f(m0 - mm0), co0 = ex2f(mo0 - mm0);
        const float ce1 = ex2f(m1 - mm1), co1 = ex2f(mo1 - mm1);
        const float rl0 = __frcp_rn(l0 * ce0 + lo0 * co0);
        const float rl1 = __frcp_rn(l1 * ce1 + lo1 * co1);

        float* O = out + ((size_t)(b * SEQ + q0 + r0 + g)) * DOUT;
#pragma unroll
        for (int j = 0; j < 8; j++) {
            const int col = j * 8 + 2 * tq;
            const float2 q0v = *(const float2*)&xo[(r0 + g) * 68 + col];
            const float2 q1v = *(const float2*)&xo[(r0 + g + 8) * 68 + col];
            *(float2*)&O[col] = make_float2(
                (o[j][0] * ce0 + q0v.x * co0) * rl0,
                (o[j][1] * ce0 + q0v.y * co0) * rl0);
            *(float2*)&O[8 * DOUT + col] = make_float2(
                (o[j][2] * ce1 + q1v.x * co1) * rl1,
                (o[j][3] * ce1 + q1v.y * co1) * rl1);
        }
    }
}

// ---------------------------------------------------------------------------
extern "C" void kernel_launch(void* const* d_in, const int* in_sizes, int n_in,
                              void* d_out, int out_size) {
    const float* x = (const float*)d_in[0];   // [4,4096,128]
    const float* w = (const float*)d_in[1];   // [3,128,64]
    float* out = (float*)d_out;               // [4,4096,64]

    cudaFuncSetAttribute(attn_kernel,
                         cudaFuncAttributeMaxDynamicSharedMemorySize, SMEM_BYTES);
    cudaFuncSetAttribute(qkv_proj_kernel,
                         cudaFuncAttributeMaxDynamicSharedMemorySize, QKV_SMEM);

    qkv_proj_kernel<<<dim3(SEQ / 128, BATCH), 512, QKV_SMEM>>>(x, w);
    attn_kernel<<<dim3(SEQ / BQ, BATCH), 512, SMEM_BYTES>>>(out);
}

// round 16
// speedup vs baseline: 1.0224x; 1.0224x over previous
#include <cuda_runtime.h>
#include <cuda_fp16.h>
#include <cstdint>

#define BATCH 4
#define SEQ   4096
#define DIN   128
#define DOUT  64
#define BQ    128
#define BK    64
#define NTILES 32          // per key-half: 2048/64

// Q pre-scale: 1/sqrt(64) * log2(e)  (softmax runs in exp2 domain)
#define QSCALE 0.1803368801111244f

// ---- fp16 scratch — device globals, no allocation ----
__device__ __half g_qh[BATCH * SEQ * DOUT];
__device__ __half g_ql[BATCH * SEQ * DOUT];
__device__ __half g_kh[BATCH * SEQ * DOUT];
__device__ __half g_kl[BATCH * SEQ * DOUT];
__device__ __half g_vt[BATCH * DOUT * SEQ];   // transposed: [b][dout][seq]

// ---- attn smem ----
#define QH_B       0
#define QL_B       18432
#define KV_B(h, s) (36864 + (h) * 82944 + (s) * 27648)
#define KH_O       0
#define KL_O       9216
#define VT_O       18432
#define SMEM_BYTES 202752

typedef unsigned long long u64;

__device__ __forceinline__ uint32_t smem_u32(const void* p) {
    uint32_t a;
    asm("{ .reg .u64 t; cvta.to.shared.u64 t, %1; cvt.u32.u64 %0, t; }" : "=r"(a) : "l"(p));
    return a;
}
__device__ __forceinline__ void cp16(uint32_t dst, const void* src) {
    asm volatile("cp.async.cg.shared.global [%0], [%1], 16;" :: "r"(dst), "l"(src));
}
#define CP_COMMIT() asm volatile("cp.async.commit_group;" ::: "memory")
#define CP_WAIT1()  asm volatile("cp.async.wait_group 1;" ::: "memory")
#define CP_WAIT2()  asm volatile("cp.async.wait_group 2;" ::: "memory")
#define BARG(id)    asm volatile("bar.sync %0, 256;" :: "r"(id) : "memory")

__device__ __forceinline__ float ex2f(float x) {
    float r; asm("ex2.approx.ftz.f32 %0, %1;" : "=f"(r) : "f"(x)); return r;
}

#define MMA16816(c, a0, a1, a2, a3, b0, b1) \
    asm volatile("mma.sync.aligned.m16n8k16.row.col.f32.f16.f16.f32 " \
                 "{%0,%1,%2,%3}, {%4,%5,%6,%7}, {%8,%9}, {%0,%1,%2,%3};" \
                 : "+f"((c)[0]), "+f"((c)[1]), "+f"((c)[2]), "+f"((c)[3]) \
                 : "r"(a0), "r"(a1), "r"(a2), "r"(a3), "r"(b0), "r"(b1))

#define LDMX4(r0, r1, r2, r3, a) \
    asm volatile("ldmatrix.sync.aligned.m8n8.x4.shared.b16 {%0,%1,%2,%3}, [%4];" \
                 : "=r"(r0), "=r"(r1), "=r"(r2), "=r"(r3) : "r"(a))

// ---------------------------------------------------------------------------
// Kernel 1: QKV projection via tensor cores (R13 structure, float4 staging).
// ---------------------------------------------------------------------------
#define QP_STRIDE 272
#define XH2_B   0
#define XL2_B   34816
#define WH2_B   69632
#define WL2_B   121856
#define VTS2_B  174080
#define VTS_PAD 136
#define QKV_SMEM 191488

__global__ __launch_bounds__(512)
void qkv_proj_kernel(const float* __restrict__ x,
                     const float* __restrict__ w) {
    extern __shared__ __align__(128) char qsm[];
    const uint32_t smb = smem_u32(qsm);
    __half* xh  = (__half*)(qsm + XH2_B);
    __half* xl  = (__half*)(qsm + XL2_B);
    __half* wh  = (__half*)(qsm + WH2_B);
    __half* wl  = (__half*)(qsm + WL2_B);
    __half* vts = (__half*)(qsm + VTS2_B);

    const int b   = blockIdx.y;
    const int n0  = blockIdx.x * 128;
    const int tid = threadIdx.x;

    // ---- stage w transposed + split; float4 LDG (e-contiguous) ----
#pragma unroll
    for (int i = 0; i < 12; i++) {
        const int i4 = tid + i * 512;           // 0..6143
        const int base = i4 << 2;
        const int p = base >> 13;
        const int d = (base >> 6) & 127;
        const int e = base & 63;
        float4 v = *(const float4*)&w[base];
        if (p == 0) { v.x *= QSCALE; v.y *= QSCALE; v.z *= QSCALE; v.w *= QSCALE; }
        const int row = p * 64 + e;
        const float vv[4] = {v.x, v.y, v.z, v.w};
#pragma unroll
        for (int k = 0; k < 4; k++) {
            const __half h = __float2half_rn(vv[k]);
            wh[(row + k) * 136 + d] = h;
            wl[(row + k) * 136 + d] = __float2half_rn(vv[k] - __half2float(h));
        }
    }
    // ---- stage x split; float4 LDG + half2 STS ----
    const float* xg = x + ((size_t)(b * SEQ + n0)) * DIN;
#pragma unroll
    for (int i = 0; i < 8; i++) {
        const int i4 = tid + i * 512;           // 0..4095
        const int tok = i4 >> 5, d4 = (i4 & 31) << 2;
        const float4 v = *(const float4*)&xg[tok * DIN + d4];
        const __half hx = __float2half_rn(v.x), hy = __float2half_rn(v.y);
        const __half hz = __float2half_rn(v.z), hw = __float2half_rn(v.w);
        *(__half2*)&xh[tok * 136 + d4]     = __halves2half2(hx, hy);
        *(__half2*)&xh[tok * 136 + d4 + 2] = __halves2half2(hz, hw);
        *(__half2*)&xl[tok * 136 + d4] = __halves2half2(
            __float2half_rn(v.x - __half2float(hx)),
            __float2half_rn(v.y - __half2float(hy)));
        *(__half2*)&xl[tok * 136 + d4 + 2] = __halves2half2(
            __float2half_rn(v.z - __half2float(hz)),
            __float2half_rn(v.w - __half2float(hw)));
    }
    __syncthreads();

    const int wid  = tid >> 5;
    const int lane = tid & 31;
    const int g    = lane >> 2;
    const int tq   = lane & 3;
    const int pairw = wid >> 1;
    const int halfn = wid & 1;
    const int r0    = pairw * 16;

    const int lt = lane >> 3, lr = lane & 7;
    const uint32_t aoff = (uint32_t)((r0 + ((lt & 1) << 3) + lr) * QP_STRIDE + ((lt >> 1) << 4));
    const uint32_t boff = (uint32_t)((((lane >> 4) << 3) + lr) * QP_STRIDE + ((lt & 1) << 4));

    float acc[12][4];
#pragma unroll
    for (int j = 0; j < 12; j++)
#pragma unroll
        for (int k = 0; k < 4; k++) acc[j][k] = 0.f;

#pragma unroll
    for (int ks = 0; ks < 8; ks++) {
        uint32_t ah0, ah1, ah2, ah3, al0, al1, al2, al3;
        LDMX4(ah0, ah1, ah2, ah3, smb + XH2_B + aoff + ks * 32);
        LDMX4(al0, al1, al2, al3, smb + XL2_B + aoff + ks * 32);
#pragma unroll
        for (int jp = 0; jp < 6; jp++) {
            const uint32_t bb = (uint32_t)((halfn * 96 + jp * 16) * QP_STRIDE) + boff + ks * 32;
            uint32_t bh0, bh1, bh2, bh3, bl0, bl1, bl2, bl3;
            LDMX4(bh0, bh1, bh2, bh3, smb + WH2_B + bb);
            LDMX4(bl0, bl1, bl2, bl3, smb + WL2_B + bb);
            MMA16816(acc[2*jp],   ah0, ah1, ah2, ah3, bh0, bh1);
            MMA16816(acc[2*jp+1], ah0, ah1, ah2, ah3, bh2, bh3);
            MMA16816(acc[2*jp],   ah0, ah1, ah2, ah3, bl0, bl1);
            MMA16816(acc[2*jp+1], ah0, ah1, ah2, ah3, bl2, bl3);
            MMA16816(acc[2*jp],   al0, al1, al2, al3, bh0, bh1);
            MMA16816(acc[2*jp+1], al0, al1, al2, al3, bh2, bh3);
        }
    }

#pragma unroll
    for (int j = 0; j < 12; j++) {
        const int col = halfn * 96 + j * 8 + 2 * tq;
        const int p = col >> 6, e = col & 63;
        const int rowA = r0 + g, rowB = r0 + g + 8;
#pragma unroll
        for (int h2 = 0; h2 < 2; h2++) {
            const int row = h2 ? rowB : rowA;
            const float v0 = acc[j][h2 * 2], v1 = acc[j][h2 * 2 + 1];
            if (p == 2) {
                vts[e * VTS_PAD + row]       = __float2half_rn(v0);
                vts[(e + 1) * VTS_PAD + row] = __float2half_rn(v1);
            } else {
                const __half h0 = __float2half_rn(v0), h1 = __float2half_rn(v1);
                const __half l0 = __float2half_rn(v0 - __half2float(h0));
                const __half l1 = __float2half_rn(v1 - __half2float(h1));
                const size_t go = (size_t)(b * SEQ + n0 + row) * DOUT + e;
                if (p == 0) {
                    *(__half2*)&g_qh[go] = __halves2half2(h0, h1);
                    *(__half2*)&g_ql[go] = __halves2half2(l0, l1);
                } else {
                    *(__half2*)&g_kh[go] = __halves2half2(h0, h1);
                    *(__half2*)&g_kl[go] = __halves2half2(l0, l1);
                }
            }
        }
    }
    __syncthreads();

    const int e = tid >> 3, seg = tid & 7;
    const __half* srcv = vts + e * VTS_PAD + seg * 16;
    uint4* dstv = (uint4*)&g_vt[(((size_t)(b * DOUT + e)) << 12) + n0 + seg * 16];
    dstv[0] = *(const uint4*)(srcv);
    dstv[1] = *(const uint4*)(srcv + 8);
}

// ---------------------------------------------------------------------------
// Kernel 2: flash attention — exact R14 best (half = wid & 1 mapping).
// ---------------------------------------------------------------------------
__device__ __forceinline__ void load_kv_h(uint32_t kb, int b, int kt, int htid) {
    const __half* kh = g_kh + ((size_t)(b * SEQ + kt)) * DOUT;
    const __half* kl = g_kl + ((size_t)(b * SEQ + kt)) * DOUT;
    const __half* vt = g_vt + (((size_t)b * DOUT) << 12) + kt;
#pragma unroll
    for (int i = 0; i < 2; i++) {
        const int id = htid + i * 256;
        const int row = id >> 3, c = id & 7;
        cp16(kb + KH_O + row * 144 + c * 16, kh + row * DOUT + c * 8);
        cp16(kb + KL_O + row * 144 + c * 16, kl + row * DOUT + c * 8);
        cp16(kb + VT_O + row * 144 + c * 16, vt + ((size_t)row << 12) + c * 8);
    }
}

__global__ __launch_bounds__(512, 1)
void attn_kernel(float* __restrict__ out) {
    extern __shared__ __align__(128) char sm[];
    const uint32_t smb = smem_u32(sm);
    const int tid  = threadIdx.x;
    const int wid  = tid >> 5;
    const int lane = tid & 31;
    const int g    = lane >> 2;
    const int tq   = lane & 3;
    const int half = wid & 1;
    const int pair = wid >> 1;
    const int htid = pair * 32 + lane;
    const int b    = blockIdx.y;
    const int q0   = blockIdx.x * BQ;
    const int r0   = pair * 16;
    const int k0   = half * 2048;

    const int lt = lane >> 3, lr = lane & 7;
    const uint32_t aoff = (uint32_t)((r0 + ((lt & 1) << 3) + lr) * 144 + ((lt >> 1) << 4));
    const uint32_t boff = (uint32_t)((((lane >> 4) << 3) + lr) * 144 + ((lt & 1) << 4));

    const uint32_t bON = (g == 0) ? 0x3C003C00u : 0u;

    {
        const __half* qh = g_qh + ((size_t)(b * SEQ + q0)) * DOUT;
        const __half* ql = g_ql + ((size_t)(b * SEQ + q0)) * DOUT;
#pragma unroll
        for (int i = 0; i < 2; i++) {
            const int id = tid + i * 512;
            const int row = id >> 3, c = id & 7;
            cp16(smb + QH_B + row * 144 + c * 16, qh + row * DOUT + c * 8);
            cp16(smb + QL_B + row * 144 + c * 16, ql + row * DOUT + c * 8);
        }
        CP_COMMIT();
        load_kv_h(smb + KV_B(half, 0), b, k0, htid);
        CP_COMMIT();
        load_kv_h(smb + KV_B(half, 1), b, k0 + BK, htid);
        CP_COMMIT();
    }
    CP_WAIT2();
    __syncthreads();

    float o[8][4], oL[4];
#pragma unroll
    for (int j = 0; j < 8; j++)
#pragma unroll
        for (int k = 0; k < 4; k++) o[j][k] = 0.f;
#pragma unroll
    for (int k = 0; k < 4; k++) oL[k] = 0.f;
    float m0 = -3.0e38f, m1 = -3.0e38f;

    for (int t = 0; t < NTILES; t++) {
        CP_WAIT1();
        BARG(1 + half);
        if (t + 2 < NTILES)
            load_kv_h(smb + KV_B(half, (t + 2) % 3), b, k0 + (t + 2) * BK, htid);
        CP_COMMIT();

        const uint32_t kvb = smb + KV_B(half, t % 3);
        const uint32_t khb = kvb + KH_O + boff;
        const uint32_t klb = kvb + KL_O + boff;
        const uint32_t vtb = kvb + VT_O + boff;

        float s[8][4];
#pragma unroll
        for (int j = 0; j < 8; j++)
#pragma unroll
            for (int k = 0; k < 4; k++) s[j][k] = 0.f;

#pragma unroll
        for (int ks = 0; ks < 4; ks++) {
            uint32_t ah0, ah1, ah2, ah3, al0, al1, al2, al3;
            LDMX4(ah0, ah1, ah2, ah3, smb + QH_B + aoff + ks * 32);
            LDMX4(al0, al1, al2, al3, smb + QL_B + aoff + ks * 32);
#pragma unroll
            for (int jp = 0; jp < 4; jp++) {
                uint32_t bh0, bh1, bh2, bh3, bl0, bl1, bl2, bl3;
                LDMX4(bh0, bh1, bh2, bh3, khb + jp * 2304 + ks * 32);
                LDMX4(bl0, bl1, bl2, bl3, klb + jp * 2304 + ks * 32);
                MMA16816(s[2*jp],   ah0, ah1, ah2, ah3, bh0, bh1);
                MMA16816(s[2*jp+1], ah0, ah1, ah2, ah3, bh2, bh3);
                MMA16816(s[2*jp],   ah0, ah1, ah2, ah3, bl0, bl1);
                MMA16816(s[2*jp+1], ah0, ah1, ah2, ah3, bl2, bl3);
                MMA16816(s[2*jp],   al0, al1, al2, al3, bh0, bh1);
                MMA16816(s[2*jp+1], al0, al1, al2, al3, bh2, bh3);
            }
        }

        float mx0 = -3.0e38f, mx1 = -3.0e38f;
#pragma unroll
        for (int j = 0; j < 8; j++) {
            mx0 = fmaxf(mx0, fmaxf(s[j][0], s[j][1]));
            mx1 = fmaxf(mx1, fmaxf(s[j][2], s[j][3]));
        }
        mx0 = fmaxf(mx0, __shfl_xor_sync(0xffffffffu, mx0, 1));
        mx0 = fmaxf(mx0, __shfl_xor_sync(0xffffffffu, mx0, 2));
        mx1 = fmaxf(mx1, __shfl_xor_sync(0xffffffffu, mx1, 1));
        mx1 = fmaxf(mx1, __shfl_xor_sync(0xffffffffu, mx1, 2));

        const bool active = __any_sync(0xffffffffu,
                                       (mx0 > m0 - 25.f) | (mx1 > m1 - 25.f));
        if (!active) continue;

        const float mn0 = fmaxf(m0, mx0), mn1 = fmaxf(m1, mx1);
        const bool upd = __any_sync(0xffffffffu, (mx0 > m0) | (mx1 > m1));
        if (upd) {
            const float c0 = ex2f(m0 - mn0), c1 = ex2f(m1 - mn1);
#pragma unroll
            for (int j = 0; j < 8; j++) {
                o[j][0] *= c0; o[j][1] *= c0;
                o[j][2] *= c1; o[j][3] *= c1;
            }
            oL[0] *= c0; oL[1] *= c0;
            oL[2] *= c1; oL[3] *= c1;
            m0 = mn0; m1 = mn1;
        }

        uint32_t pa[4][4];
#pragma unroll
        for (int j = 0; j < 8; j++) {
            const float e0 = ex2f(s[j][0] - m0), e1 = ex2f(s[j][1] - m0);
            const float e2 = ex2f(s[j][2] - m1), e3 = ex2f(s[j][3] - m1);
            const __half2 h01 = __floats2half2_rn(e0, e1);
            const __half2 h23 = __floats2half2_rn(e2, e3);
            pa[j >> 1][(j & 1) * 2 + 0] = *(const uint32_t*)&h01;
            pa[j >> 1][(j & 1) * 2 + 1] = *(const uint32_t*)&h23;
        }

#pragma unroll
        for (int ks = 0; ks < 4; ks++) {
#pragma unroll
            for (int jp = 0; jp < 4; jp++) {
                uint32_t v0, v1, v2, v3;
                LDMX4(v0, v1, v2, v3, vtb + jp * 2304 + ks * 32);
                MMA16816(o[2*jp],   pa[ks][0], pa[ks][1], pa[ks][2], pa[ks][3], v0, v1);
                MMA16816(o[2*jp+1], pa[ks][0], pa[ks][1], pa[ks][2], pa[ks][3], v2, v3);
            }
            MMA16816(oL, pa[ks][0], pa[ks][1], pa[ks][2], pa[ks][3], bON, bON);
        }
    }

    const int qlead = lane & ~3;
    const float l0 = __shfl_sync(0xffffffffu, oL[0], qlead);
    const float l1 = __shfl_sync(0xffffffffu, oL[2], qlead);

    __syncthreads();
    float* xo = (float*)sm;
    float* xm = (float*)(sm + 8 * 16 * 68 * 4);

    if (half == 1) {
#pragma unroll
        for (int j = 0; j < 8; j++) {
            const int col = j * 8 + 2 * tq;
            *(float2*)&xo[(r0 + g) * 68 + col]     = make_float2(o[j][0], o[j][1]);
            *(float2*)&xo[(r0 + g + 8) * 68 + col] = make_float2(o[j][2], o[j][3]);
        }
        if (tq == 0) {
            xm[(r0 + g) * 2]         = m0;  xm[(r0 + g) * 2 + 1]     = l0;
            xm[(r0 + g + 8) * 2]     = m1;  xm[(r0 + g + 8) * 2 + 1] = l1;
        }
    }
    __syncthreads();

    if (half == 0) {
        const float mo0 = xm[(r0 + g) * 2],     lo0 = xm[(r0 + g) * 2 + 1];
        const float mo1 = xm[(r0 + g + 8) * 2], lo1 = xm[(r0 + g + 8) * 2 + 1];
        const float mm0 = fmaxf(m0, mo0), mm1 = fmaxf(m1, mo1);
        const float ce0 = ex2f(m0 - mm0), co0 = ex2f(mo0 - mm0);
        const float ce1 = ex2f(m1 - mm1), co1 = ex2f(mo1 - mm1);
        const float rl0 = __frcp_rn(l0 * ce0 + lo0 * co0);
        const float rl1 = __frcp_rn(l1 * ce1 + lo1 * co1);

        float* O = out + ((size_t)(b * SEQ + q0 + r0 + g)) * DOUT;
#pragma unroll
        for (int j = 0; j < 8; j++) {
            const int col = j * 8 + 2 * tq;
            const float2 q0v = *(const float2*)&xo[(r0 + g) * 68 + col];
            const float2 q1v = *(const float2*)&xo[(r0 + g + 8) * 68 + col];
            *(float2*)&O[col] = make_float2(
                (o[j][0] * ce0 + q0v.x * co0) * rl0,
                (o[j][1] * ce0 + q0v.y * co0) * rl0);
            *(float2*)&O[8 * DOUT + col] = make_float2(
                (o[j][2] * ce1 + q1v.x * co1) * rl1,
                (o[j][3] * ce1 + q1v.y * co1) * rl1);
        }
    }
}

// ---------------------------------------------------------------------------
extern "C" void kernel_launch(void* const* d_in, const int* in_sizes, int n_in,
                              void* d_out, int out_size) {
    const float* x = (const float*)d_in[0];   // [4,4096,128]
    const float* w = (const float*)d_in[1];   // [3,128,64]
    float* out = (float*)d_out;               // [4,4096,64]

    cudaFuncSetAttribute(attn_kernel,
                         cudaFuncAttributeMaxDynamicSharedMemorySize, SMEM_BYTES);
    cudaFuncSetAttribute(qkv_proj_kernel,
                         cudaFuncAttributeMaxDynamicSharedMemorySize, QKV_SMEM);

    qkv_proj_kernel<<<dim3(SEQ / 128, BATCH), 512, QKV_SMEM>>>(x, w);
    attn_kernel<<<dim3(SEQ / BQ, BATCH), 512, SMEM_BYTES>>>(out);
}

// round 17
// speedup vs baseline: 1.0559x; 1.0328x over previous
#include <cuda_runtime.h>
#include <cuda_fp16.h>
#include <cstdint>

#define BATCH 4
#define SEQ   4096
#define DIN   128
#define DOUT  64
#define BQ    128
#define BK    64
#define NTILES 32          // per key-half: 2048/64

// Q pre-scale: 1/sqrt(64) * log2(e)  (softmax runs in exp2 domain)
#define QSCALE 0.1803368801111244f

// ---- fp16 scratch — device globals, no allocation ----
__device__ __half g_qh[BATCH * SEQ * DOUT];
__device__ __half g_ql[BATCH * SEQ * DOUT];
__device__ __half g_kh[BATCH * SEQ * DOUT];
__device__ __half g_kl[BATCH * SEQ * DOUT];
__device__ __half g_vt[BATCH * DOUT * SEQ];   // transposed: [b][dout][seq]
// pre-split w in padded smem layout: [pcol = p*64+e][d], 136 halves/row
__device__ __align__(16) __half g_wh2[192 * 136];
__device__ __align__(16) __half g_wl2[192 * 136];

// ---- attn smem ----
#define QH_B       0
#define QL_B       18432
#define KV_B(h, s) (36864 + (h) * 82944 + (s) * 27648)
#define KH_O       0
#define KL_O       9216
#define VT_O       18432
#define SMEM_BYTES 202752

typedef unsigned long long u64;

__device__ __forceinline__ uint32_t smem_u32(const void* p) {
    uint32_t a;
    asm("{ .reg .u64 t; cvta.to.shared.u64 t, %1; cvt.u32.u64 %0, t; }" : "=r"(a) : "l"(p));
    return a;
}
__device__ __forceinline__ void cp16(uint32_t dst, const void* src) {
    asm volatile("cp.async.cg.shared.global [%0], [%1], 16;" :: "r"(dst), "l"(src));
}
#define CP_COMMIT() asm volatile("cp.async.commit_group;" ::: "memory")
#define CP_WAIT0()  asm volatile("cp.async.wait_group 0;" ::: "memory")
#define CP_WAIT1()  asm volatile("cp.async.wait_group 1;" ::: "memory")
#define CP_WAIT2()  asm volatile("cp.async.wait_group 2;" ::: "memory")
#define BARG(id)    asm volatile("bar.sync %0, 256;" :: "r"(id) : "memory")

__device__ __forceinline__ float ex2f(float x) {
    float r; asm("ex2.approx.ftz.f32 %0, %1;" : "=f"(r) : "f"(x)); return r;
}

#define MMA16816(c, a0, a1, a2, a3, b0, b1) \
    asm volatile("mma.sync.aligned.m16n8k16.row.col.f32.f16.f16.f32 " \
                 "{%0,%1,%2,%3}, {%4,%5,%6,%7}, {%8,%9}, {%0,%1,%2,%3};" \
                 : "+f"((c)[0]), "+f"((c)[1]), "+f"((c)[2]), "+f"((c)[3]) \
                 : "r"(a0), "r"(a1), "r"(a2), "r"(a3), "r"(b0), "r"(b1))

#define LDMX4(r0, r1, r2, r3, a) \
    asm volatile("ldmatrix.sync.aligned.m8n8.x4.shared.b16 {%0,%1,%2,%3}, [%4];" \
                 : "=r"(r0), "=r"(r1), "=r"(r2), "=r"(r3) : "r"(a))

// ---------------------------------------------------------------------------
// Kernel 0: one-time w split into the padded layout (QSCALE folded into Q).
// ---------------------------------------------------------------------------
__global__ __launch_bounds__(512)
void w_prep_kernel(const float* __restrict__ w) {
    const int idx = blockIdx.x * 512 + threadIdx.x;   // 0..24575
    if (idx >= 3 * DIN * DOUT) return;
    const int p = idx >> 13;
    const int rem = idx & 8191;
    const int d = rem >> 6, e = rem & 63;
    float v = w[idx];
    if (p == 0) v *= QSCALE;
    const __half h = __float2half_rn(v);
    const int row = p * 64 + e;
    g_wh2[row * 136 + d] = h;
    g_wl2[row * 136 + d] = __float2half_rn(v - __half2float(h));
}

// ---------------------------------------------------------------------------
// Kernel 1: QKV projection via tensor cores; w staged via cp.async from the
// pre-split arrays (no per-CTA conversion), x split staged float4->half2.
// ---------------------------------------------------------------------------
#define QP_STRIDE 272
#define XH2_B   0
#define XL2_B   34816
#define WH2_B   69632
#define WL2_B   121856
#define VTS2_B  174080
#define VTS_PAD 136
#define QKV_SMEM 191488
#define W_CHUNKS (192 * 136 * 2 / 16)    // 3264 16B chunks per array

__global__ __launch_bounds__(512)
void qkv_proj_kernel(const float* __restrict__ x) {
    extern __shared__ __align__(128) char qsm[];
    const uint32_t smb = smem_u32(qsm);
    __half* xh  = (__half*)(qsm + XH2_B);
    __half* xl  = (__half*)(qsm + XL2_B);
    __half* vts = (__half*)(qsm + VTS2_B);

    const int b   = blockIdx.y;
    const int n0  = blockIdx.x * 128;
    const int tid = threadIdx.x;

    // ---- stage pre-split w via cp.async (fully coalesced 16B) ----
#pragma unroll
    for (int i = 0; i < 13; i++) {
        const int c = tid + i * 512;             // 0..6527
        if (c < W_CHUNKS) {
            cp16(smb + WH2_B + c * 16, (const char*)g_wh2 + c * 16);
        } else if (c < 2 * W_CHUNKS) {
            const int c2 = c - W_CHUNKS;
            cp16(smb + WL2_B + c2 * 16, (const char*)g_wl2 + c2 * 16);
        }
    }
    CP_COMMIT();

    // ---- stage x split; float4 LDG + half2 STS ----
    const float* xg = x + ((size_t)(b * SEQ + n0)) * DIN;
#pragma unroll
    for (int i = 0; i < 8; i++) {
        const int i4 = tid + i * 512;            // 0..4095
        const int tok = i4 >> 5, d4 = (i4 & 31) << 2;
        const float4 v = *(const float4*)&xg[tok * DIN + d4];
        const __half hx = __float2half_rn(v.x), hy = __float2half_rn(v.y);
        const __half hz = __float2half_rn(v.z), hw = __float2half_rn(v.w);
        *(__half2*)&xh[tok * 136 + d4]     = __halves2half2(hx, hy);
        *(__half2*)&xh[tok * 136 + d4 + 2] = __halves2half2(hz, hw);
        *(__half2*)&xl[tok * 136 + d4] = __halves2half2(
            __float2half_rn(v.x - __half2float(hx)),
            __float2half_rn(v.y - __half2float(hy)));
        *(__half2*)&xl[tok * 136 + d4 + 2] = __halves2half2(
            __float2half_rn(v.z - __half2float(hz)),
            __float2half_rn(v.w - __half2float(hw)));
    }
    CP_WAIT0();
    __syncthreads();

    const int wid  = tid >> 5;
    const int lane = tid & 31;
    const int g    = lane >> 2;
    const int tq   = lane & 3;
    const int pairw = wid >> 1;
    const int halfn = wid & 1;
    const int r0    = pairw * 16;

    const int lt = lane >> 3, lr = lane & 7;
    const uint32_t aoff = (uint32_t)((r0 + ((lt & 1) << 3) + lr) * QP_STRIDE + ((lt >> 1) << 4));
    const uint32_t boff = (uint32_t)((((lane >> 4) << 3) + lr) * QP_STRIDE + ((lt & 1) << 4));

    float acc[12][4];
#pragma unroll
    for (int j = 0; j < 12; j++)
#pragma unroll
        for (int k = 0; k < 4; k++) acc[j][k] = 0.f;

#pragma unroll
    for (int ks = 0; ks < 8; ks++) {
        uint32_t ah0, ah1, ah2, ah3, al0, al1, al2, al3;
        LDMX4(ah0, ah1, ah2, ah3, smb + XH2_B + aoff + ks * 32);
        LDMX4(al0, al1, al2, al3, smb + XL2_B + aoff + ks * 32);
#pragma unroll
        for (int jp = 0; jp < 6; jp++) {
            const uint32_t bb = (uint32_t)((halfn * 96 + jp * 16) * QP_STRIDE) + boff + ks * 32;
            uint32_t bh0, bh1, bh2, bh3, bl0, bl1, bl2, bl3;
            LDMX4(bh0, bh1, bh2, bh3, smb + WH2_B + bb);
            LDMX4(bl0, bl1, bl2, bl3, smb + WL2_B + bb);
            MMA16816(acc[2*jp],   ah0, ah1, ah2, ah3, bh0, bh1);
            MMA16816(acc[2*jp+1], ah0, ah1, ah2, ah3, bh2, bh3);
            MMA16816(acc[2*jp],   ah0, ah1, ah2, ah3, bl0, bl1);
            MMA16816(acc[2*jp+1], ah0, ah1, ah2, ah3, bl2, bl3);
            MMA16816(acc[2*jp],   al0, al1, al2, al3, bh0, bh1);
            MMA16816(acc[2*jp+1], al0, al1, al2, al3, bh2, bh3);
        }
    }

#pragma unroll
    for (int j = 0; j < 12; j++) {
        const int col = halfn * 96 + j * 8 + 2 * tq;
        const int p = col >> 6, e = col & 63;
        const int rowA = r0 + g, rowB = r0 + g + 8;
#pragma unroll
        for (int h2 = 0; h2 < 2; h2++) {
            const int row = h2 ? rowB : rowA;
            const float v0 = acc[j][h2 * 2], v1 = acc[j][h2 * 2 + 1];
            if (p == 2) {
                vts[e * VTS_PAD + row]       = __float2half_rn(v0);
                vts[(e + 1) * VTS_PAD + row] = __float2half_rn(v1);
            } else {
                const __half h0 = __float2half_rn(v0), h1 = __float2half_rn(v1);
                const __half l0 = __float2half_rn(v0 - __half2float(h0));
                const __half l1 = __float2half_rn(v1 - __half2float(h1));
                const size_t go = (size_t)(b * SEQ + n0 + row) * DOUT + e;
                if (p == 0) {
                    *(__half2*)&g_qh[go] = __halves2half2(h0, h1);
                    *(__half2*)&g_ql[go] = __halves2half2(l0, l1);
                } else {
                    *(__half2*)&g_kh[go] = __halves2half2(h0, h1);
                    *(__half2*)&g_kl[go] = __halves2half2(l0, l1);
                }
            }
        }
    }
    __syncthreads();

    const int e = tid >> 3, seg = tid & 7;
    const __half* srcv = vts + e * VTS_PAD + seg * 16;
    uint4* dstv = (uint4*)&g_vt[(((size_t)(b * DOUT + e)) << 12) + n0 + seg * 16];
    dstv[0] = *(const uint4*)(srcv);
    dstv[1] = *(const uint4*)(srcv + 8);
}

// ---------------------------------------------------------------------------
// Kernel 2: flash attention — exact R14 best (half = wid & 1 mapping).
// ---------------------------------------------------------------------------
__device__ __forceinline__ void load_kv_h(uint32_t kb, int b, int kt, int htid) {
    const __half* kh = g_kh + ((size_t)(b * SEQ + kt)) * DOUT;
    const __half* kl = g_kl + ((size_t)(b * SEQ + kt)) * DOUT;
    const __half* vt = g_vt + (((size_t)b * DOUT) << 12) + kt;
#pragma unroll
    for (int i = 0; i < 2; i++) {
        const int id = htid + i * 256;
        const int row = id >> 3, c = id & 7;
        cp16(kb + KH_O + row * 144 + c * 16, kh + row * DOUT + c * 8);
        cp16(kb + KL_O + row * 144 + c * 16, kl + row * DOUT + c * 8);
        cp16(kb + VT_O + row * 144 + c * 16, vt + ((size_t)row << 12) + c * 8);
    }
}

__global__ __launch_bounds__(512, 1)
void attn_kernel(float* __restrict__ out) {
    extern __shared__ __align__(128) char sm[];
    const uint32_t smb = smem_u32(sm);
    const int tid  = threadIdx.x;
    const int wid  = tid >> 5;
    const int lane = tid & 31;
    const int g    = lane >> 2;
    const int tq   = lane & 3;
    const int half = wid & 1;
    const int pair = wid >> 1;
    const int htid = pair * 32 + lane;
    const int b    = blockIdx.y;
    const int q0   = blockIdx.x * BQ;
    const int r0   = pair * 16;
    const int k0   = half * 2048;

    const int lt = lane >> 3, lr = lane & 7;
    const uint32_t aoff = (uint32_t)((r0 + ((lt & 1) << 3) + lr) * 144 + ((lt >> 1) << 4));
    const uint32_t boff = (uint32_t)((((lane >> 4) << 3) + lr) * 144 + ((lt & 1) << 4));

    const uint32_t bON = (g == 0) ? 0x3C003C00u : 0u;

    {
        const __half* qh = g_qh + ((size_t)(b * SEQ + q0)) * DOUT;
        const __half* ql = g_ql + ((size_t)(b * SEQ + q0)) * DOUT;
#pragma unroll
        for (int i = 0; i < 2; i++) {
            const int id = tid + i * 512;
            const int row = id >> 3, c = id & 7;
            cp16(smb + QH_B + row * 144 + c * 16, qh + row * DOUT + c * 8);
            cp16(smb + QL_B + row * 144 + c * 16, ql + row * DOUT + c * 8);
        }
        CP_COMMIT();
        load_kv_h(smb + KV_B(half, 0), b, k0, htid);
        CP_COMMIT();
        load_kv_h(smb + KV_B(half, 1), b, k0 + BK, htid);
        CP_COMMIT();
    }
    CP_WAIT2();
    __syncthreads();

    float o[8][4], oL[4];
#pragma unroll
    for (int j = 0; j < 8; j++)
#pragma unroll
        for (int k = 0; k < 4; k++) o[j][k] = 0.f;
#pragma unroll
    for (int k = 0; k < 4; k++) oL[k] = 0.f;
    float m0 = -3.0e38f, m1 = -3.0e38f;

    for (int t = 0; t < NTILES; t++) {
        CP_WAIT1();
        BARG(1 + half);
        if (t + 2 < NTILES)
            load_kv_h(smb + KV_B(half, (t + 2) % 3), b, k0 + (t + 2) * BK, htid);
        CP_COMMIT();

        const uint32_t kvb = smb + KV_B(half, t % 3);
        const uint32_t khb = kvb + KH_O + boff;
        const uint32_t klb = kvb + KL_O + boff;
        const uint32_t vtb = kvb + VT_O + boff;

        float s[8][4];
#pragma unroll
        for (int j = 0; j < 8; j++)
#pragma unroll
            for (int k = 0; k < 4; k++) s[j][k] = 0.f;

#pragma unroll
        for (int ks = 0; ks < 4; ks++) {
            uint32_t ah0, ah1, ah2, ah3, al0, al1, al2, al3;
            LDMX4(ah0, ah1, ah2, ah3, smb + QH_B + aoff + ks * 32);
            LDMX4(al0, al1, al2, al3, smb + QL_B + aoff + ks * 32);
#pragma unroll
            for (int jp = 0; jp < 4; jp++) {
                uint32_t bh0, bh1, bh2, bh3, bl0, bl1, bl2, bl3;
                LDMX4(bh0, bh1, bh2, bh3, khb + jp * 2304 + ks * 32);
                LDMX4(bl0, bl1, bl2, bl3, klb + jp * 2304 + ks * 32);
                MMA16816(s[2*jp],   ah0, ah1, ah2, ah3, bh0, bh1);
                MMA16816(s[2*jp+1], ah0, ah1, ah2, ah3, bh2, bh3);
                MMA16816(s[2*jp],   ah0, ah1, ah2, ah3, bl0, bl1);
                MMA16816(s[2*jp+1], ah0, ah1, ah2, ah3, bl2, bl3);
                MMA16816(s[2*jp],   al0, al1, al2, al3, bh0, bh1);
                MMA16816(s[2*jp+1], al0, al1, al2, al3, bh2, bh3);
            }
        }

        float mx0 = -3.0e38f, mx1 = -3.0e38f;
#pragma unroll
        for (int j = 0; j < 8; j++) {
            mx0 = fmaxf(mx0, fmaxf(s[j][0], s[j][1]));
            mx1 = fmaxf(mx1, fmaxf(s[j][2], s[j][3]));
        }
        mx0 = fmaxf(mx0, __shfl_xor_sync(0xffffffffu, mx0, 1));
        mx0 = fmaxf(mx0, __shfl_xor_sync(0xffffffffu, mx0, 2));
        mx1 = fmaxf(mx1, __shfl_xor_sync(0xffffffffu, mx1, 1));
        mx1 = fmaxf(mx1, __shfl_xor_sync(0xffffffffu, mx1, 2));

        const bool active = __any_sync(0xffffffffu,
                                       (mx0 > m0 - 25.f) | (mx1 > m1 - 25.f));
        if (!active) continue;

        const float mn0 = fmaxf(m0, mx0), mn1 = fmaxf(m1, mx1);
        const bool upd = __any_sync(0xffffffffu, (mx0 > m0) | (mx1 > m1));
        if (upd) {
            const float c0 = ex2f(m0 - mn0), c1 = ex2f(m1 - mn1);
#pragma unroll
            for (int j = 0; j < 8; j++) {
                o[j][0] *= c0; o[j][1] *= c0;
                o[j][2] *= c1; o[j][3] *= c1;
            }
            oL[0] *= c0; oL[1] *= c0;
            oL[2] *= c1; oL[3] *= c1;
            m0 = mn0; m1 = mn1;
        }

        uint32_t pa[4][4];
#pragma unroll
        for (int j = 0; j < 8; j++) {
            const float e0 = ex2f(s[j][0] - m0), e1 = ex2f(s[j][1] - m0);
            const float e2 = ex2f(s[j][2] - m1), e3 = ex2f(s[j][3] - m1);
            const __half2 h01 = __floats2half2_rn(e0, e1);
            const __half2 h23 = __floats2half2_rn(e2, e3);
            pa[j >> 1][(j & 1) * 2 + 0] = *(const uint32_t*)&h01;
            pa[j >> 1][(j & 1) * 2 + 1] = *(const uint32_t*)&h23;
        }

#pragma unroll
        for (int ks = 0; ks < 4; ks++) {
#pragma unroll
            for (int jp = 0; jp < 4; jp++) {
                uint32_t v0, v1, v2, v3;
                LDMX4(v0, v1, v2, v3, vtb + jp * 2304 + ks * 32);
                MMA16816(o[2*jp],   pa[ks][0], pa[ks][1], pa[ks][2], pa[ks][3], v0, v1);
                MMA16816(o[2*jp+1], pa[ks][0], pa[ks][1], pa[ks][2], pa[ks][3], v2, v3);
            }
            MMA16816(oL, pa[ks][0], pa[ks][1], pa[ks][2], pa[ks][3], bON, bON);
        }
    }

    const int qlead = lane & ~3;
    const float l0 = __shfl_sync(0xffffffffu, oL[0], qlead);
    const float l1 = __shfl_sync(0xffffffffu, oL[2], qlead);

    __syncthreads();
    float* xo = (float*)sm;
    float* xm = (float*)(sm + 8 * 16 * 68 * 4);

    if (half == 1) {
#pragma unroll
        for (int j = 0; j < 8; j++) {
            const int col = j * 8 + 2 * tq;
            *(float2*)&xo[(r0 + g) * 68 + col]     = make_float2(o[j][0], o[j][1]);
            *(float2*)&xo[(r0 + g + 8) * 68 + col] = make_float2(o[j][2], o[j][3]);
        }
        if (tq == 0) {
            xm[(r0 + g) * 2]         = m0;  xm[(r0 + g) * 2 + 1]     = l0;
            xm[(r0 + g + 8) * 2]     = m1;  xm[(r0 + g + 8) * 2 + 1] = l1;
        }
    }
    __syncthreads();

    if (half == 0) {
        const float mo0 = xm[(r0 + g) * 2],     lo0 = xm[(r0 + g) * 2 + 1];
        const float mo1 = xm[(r0 + g + 8) * 2], lo1 = xm[(r0 + g + 8) * 2 + 1];
        const float mm0 = fmaxf(m0, mo0), mm1 = fmaxf(m1, mo1);
        const float ce0 = ex2f(m0 - mm0), co0 = ex2f(mo0 - mm0);
        const float ce1 = ex2f(m1 - mm1), co1 = ex2f(mo1 - mm1);
        const float rl0 = __frcp_rn(l0 * ce0 + lo0 * co0);
        const float rl1 = __frcp_rn(l1 * ce1 + lo1 * co1);

        float* O = out + ((size_t)(b * SEQ + q0 + r0 + g)) * DOUT;
#pragma unroll
        for (int j = 0; j < 8; j++) {
            const int col = j * 8 + 2 * tq;
            const float2 q0v = *(const float2*)&xo[(r0 + g) * 68 + col];
            const float2 q1v = *(const float2*)&xo[(r0 + g + 8) * 68 + col];
            *(float2*)&O[col] = make_float2(
                (o[j][0] * ce0 + q0v.x * co0) * rl0,
                (o[j][1] * ce0 + q0v.y * co0) * rl0);
            *(float2*)&O[8 * DOUT + col] = make_float2(
                (o[j][2] * ce1 + q1v.x * co1) * rl1,
                (o[j][3] * ce1 + q1v.y * co1) * rl1);
        }
    }
}

// ---------------------------------------------------------------------------
extern "C" void kernel_launch(void* const* d_in, const int* in_sizes, int n_in,
                              void* d_out, int out_size) {
    const float* x = (const float*)d_in[0];   // [4,4096,128]
    const float* w = (const float*)d_in[1];   // [3,128,64]
    float* out = (float*)d_out;               // [4,4096,64]

    cudaFuncSetAttribute(attn_kernel,
                         cudaFuncAttributeMaxDynamicSharedMemorySize, SMEM_BYTES);
    cudaFuncSetAttribute(qkv_proj_kernel,
                         cudaFuncAttributeMaxDynamicSharedMemorySize, QKV_SMEM);

    w_prep_kernel<<<48, 512>>>(w);
    qkv_proj_kernel<<<dim3(SEQ / 128, BATCH), 512, QKV_SMEM>>>(x);
    attn_kernel<<<dim3(SEQ / BQ, BATCH), 512, SMEM_BYTES>>>(out);
}